// round 1
// baseline (speedup 1.0000x reference)
#include <cuda_runtime.h>
#include <math.h>

// Problem dims
#define Bb 8
#define Nn_SEQ 1024
#define Dd 256
#define Hh 4
#define EPSF 1e-6f

// ---------------- scratch (device globals; no allocation allowed) ----------
__device__ float g_xnorm[Bb * Nn_SEQ * Dd];                 // 8 MB
__device__ float g_q[Hh * Bb * Nn_SEQ * Dd];                // 32 MB
__device__ float g_k[Hh * Bb * Nn_SEQ * Dd];
__device__ float g_v[Hh * Bb * Nn_SEQ * Dd];
__device__ float g_gt[Hh * Bb * Nn_SEQ * Dd];
__device__ float g_o[Hh * Bb * Nn_SEQ * Dd];
__device__ float g_att[(long long)Hh * Bb * Nn_SEQ * Nn_SEQ]; // 128 MB
__device__ float g_cat[Bb * Nn_SEQ * Dd * Hh];              // 32 MB
__device__ float g_tmp[Bb * Nn_SEQ * Dd];                   // 8 MB

// ---------------- reductions (blocks of exactly 256 threads) ---------------
__device__ __forceinline__ float warpSum(float v) {
    v += __shfl_down_sync(0xffffffffu, v, 16);
    v += __shfl_down_sync(0xffffffffu, v, 8);
    v += __shfl_down_sync(0xffffffffu, v, 4);
    v += __shfl_down_sync(0xffffffffu, v, 2);
    v += __shfl_down_sync(0xffffffffu, v, 1);
    return v;
}
__device__ __forceinline__ float warpMax(float v) {
    v = fmaxf(v, __shfl_down_sync(0xffffffffu, v, 16));
    v = fmaxf(v, __shfl_down_sync(0xffffffffu, v, 8));
    v = fmaxf(v, __shfl_down_sync(0xffffffffu, v, 4));
    v = fmaxf(v, __shfl_down_sync(0xffffffffu, v, 2));
    v = fmaxf(v, __shfl_down_sync(0xffffffffu, v, 1));
    return v;
}
__device__ float blockSum256(float v) {
    __shared__ float s[8];
    int w = threadIdx.x >> 5, l = threadIdx.x & 31;
    v = warpSum(v);
    if (l == 0) s[w] = v;
    __syncthreads();
    if (w == 0) {
        float t = (l < 8) ? s[l] : 0.f;
        t = warpSum(t);
        if (l == 0) s[0] = t;
    }
    __syncthreads();
    float r = s[0];
    __syncthreads();
    return r;
}
__device__ float blockMax256(float v) {
    __shared__ float s[8];
    int w = threadIdx.x >> 5, l = threadIdx.x & 31;
    v = warpMax(v);
    if (l == 0) s[w] = v;
    __syncthreads();
    if (w == 0) {
        float t = (l < 8) ? s[l] : -3.4e38f;
        t = warpMax(t);
        if (l == 0) s[0] = t;
    }
    __syncthreads();
    float r = s[0];
    __syncthreads();
    return r;
}

// ---------------- kernel 1: LayerNorm(x) -> g_xnorm ------------------------
__global__ void ln_x_kernel(const float* __restrict__ x,
                            const float* __restrict__ g, const float* __restrict__ b) {
    long long row = blockIdx.x;
    int t = threadIdx.x;
    float v = x[row * Dd + t];
    float mean = blockSum256(v) * (1.0f / Dd);
    float d = v - mean;
    float var = blockSum256(d * d) * (1.0f / Dd);
    g_xnorm[row * Dd + t] = d * rsqrtf(var + EPSF) * g[t] + b[t];
}

// ---------------- generic tiled SGEMM --------------------------------------
// C[M,Nc] = alpha * A[M,K] @ (B or B^T), all row-major.
// BM=BN=128, BK=16, 256 threads, 8x8 microtile (strided by 16).
#define BM 128
#define BN 128
#define BK 16

__global__ __launch_bounds__(256, 2)
void sgemm_kernel(const float* __restrict__ A, const float* __restrict__ Bm,
                  float* __restrict__ C, int M, int Nc, int K,
                  float alpha, int transB,
                  long long bsA, long long bsB, long long bsC) {
    A  += (long long)blockIdx.z * bsA;
    Bm += (long long)blockIdx.z * bsB;
    C  += (long long)blockIdx.z * bsC;
    int m0 = blockIdx.y * BM;
    int n0 = blockIdx.x * BN;

    __shared__ float As[BK][BM + 1];
    __shared__ float Bs[BK][BN + 1];

    int tid = threadIdx.x;
    int tx = tid & 15, ty = tid >> 4;

    float acc[8][8];
#pragma unroll
    for (int i = 0; i < 8; ++i)
#pragma unroll
        for (int j = 0; j < 8; ++j) acc[i][j] = 0.f;

    for (int k0 = 0; k0 < K; k0 += BK) {
        // load A tile (128x16): kc = tid&15, mr = tid>>4
        {
            int kc = tid & 15, mr = tid >> 4;
#pragma unroll
            for (int p = 0; p < 8; ++p)
                As[kc][mr + 16 * p] =
                    A[(long long)(m0 + mr + 16 * p) * K + (k0 + kc)];
        }
        if (!transB) {
            int nc = tid & 127, kr = tid >> 7;
#pragma unroll
            for (int p = 0; p < 8; ++p)
                Bs[kr + 2 * p][nc] =
                    Bm[(long long)(k0 + kr + 2 * p) * Nc + (n0 + nc)];
        } else {
            int kc = tid & 15, nr = tid >> 4;
#pragma unroll
            for (int p = 0; p < 8; ++p)
                Bs[kc][nr + 16 * p] =
                    Bm[(long long)(n0 + nr + 16 * p) * K + (k0 + kc)];
        }
        __syncthreads();

#pragma unroll
        for (int kk = 0; kk < BK; ++kk) {
            float a[8], bv[8];
#pragma unroll
            for (int i = 0; i < 8; ++i) a[i] = As[kk][ty + 16 * i];
#pragma unroll
            for (int j = 0; j < 8; ++j) bv[j] = Bs[kk][tx + 16 * j];
#pragma unroll
            for (int i = 0; i < 8; ++i)
#pragma unroll
                for (int j = 0; j < 8; ++j) acc[i][j] += a[i] * bv[j];
        }
        __syncthreads();
    }

#pragma unroll
    for (int i = 0; i < 8; ++i)
#pragma unroll
        for (int j = 0; j < 8; ++j)
            C[(long long)(m0 + ty + 16 * i) * Nc + (n0 + tx + 16 * j)] =
                alpha * acc[i][j];
}

// ---------------- kernel: masked softmax over att rows ---------------------
// one block per (h,b,n) row of length N
__global__ void softmax_kernel(const int* __restrict__ mask) {
    int r = blockIdx.x;                       // (h*B + b)*N + n
    int n = r & (Nn_SEQ - 1);
    int hb = r >> 10;
    int b = hb & (Bb - 1);
    float* row = g_att + (long long)r * Nn_SEQ;
    int t = threadIdx.x;

    int mn = mask[b * Nn_SEQ + n];
    float s[4];
    int am[4];
    float mx = -3.4e38f;
#pragma unroll
    for (int i = 0; i < 4; ++i) {
        int idx = t + 256 * i;
        int mm = mask[b * Nn_SEQ + idx];
        am[i] = mn * mm;
        float v = row[idx];
        v = v + (1.0f - (float)am[i]) * (-1e9f);
        s[i] = v;
        mx = fmaxf(mx, v);
    }
    mx = blockMax256(mx);
    float lsum = 0.f;
#pragma unroll
    for (int i = 0; i < 4; ++i) {
        s[i] = expf(s[i] - mx);
        lsum += s[i];
    }
    float tot = blockSum256(lsum);
    float inv = 1.0f / tot;
#pragma unroll
    for (int i = 0; i < 4; ++i) {
        int idx = t + 256 * i;
        row[idx] = am[i] ? s[i] * inv : 0.0f;
    }
}

// ---------------- kernel: gate * out + x, LN(lnr), scatter to concat -------
// one block per (h,b,n) row of length D
__global__ void gate_res_ln_kernel(const float* __restrict__ x,
                                   const float* __restrict__ lg,
                                   const float* __restrict__ lb) {
    int r = blockIdx.x;                       // (h*B + b)*N + n
    int t = threadIdx.x;
    int n = r & (Nn_SEQ - 1);
    int hb = r >> 10;
    int b = hb & (Bb - 1);
    int h = hb >> 3;
    long long idx = (long long)r * Dd + t;
    long long xrow = (long long)(b * Nn_SEQ + n) * Dd;

    float gv = g_gt[idx];
    float sig = 1.0f / (1.0f + expf(-gv));
    float val = g_o[idx] * sig + x[xrow + t];

    float mean = blockSum256(val) * (1.0f / Dd);
    float d = val - mean;
    float var = blockSum256(d * d) * (1.0f / Dd);
    float res = d * rsqrtf(var + EPSF) * lg[t] + lb[t];

    // concat layout: feature index = e*H + h
    g_cat[(long long)(b * Nn_SEQ + n) * (Dd * Hh) + t * Hh + h] = res;
}

// ---------------- kernel: + bias + x, LN(lno), * mask -> out ---------------
__global__ void final_kernel(const float* __restrict__ x,
                             const float* __restrict__ ob,
                             const float* __restrict__ lg,
                             const float* __restrict__ lb,
                             const int* __restrict__ mask,
                             float* __restrict__ out) {
    int r = blockIdx.x;                       // b*N + n
    int t = threadIdx.x;
    long long idx = (long long)r * Dd + t;
    float val = g_tmp[idx] + ob[t] + x[idx];
    float mean = blockSum256(val) * (1.0f / Dd);
    float d = val - mean;
    float var = blockSum256(d * d) * (1.0f / Dd);
    float res = d * rsqrtf(var + EPSF) * lg[t] + lb[t];
    out[idx] = res * (float)mask[r];
}

// ---------------- launch ----------------------------------------------------
extern "C" void kernel_launch(void* const* d_in, const int* in_sizes, int n_in,
                              void* d_out, int out_size) {
    const float* x     = (const float*)d_in[0];
    const int*   mask  = (const int*)d_in[1];
    const float* wq    = (const float*)d_in[2];
    const float* wk    = (const float*)d_in[3];
    const float* wv    = (const float*)d_in[4];
    const float* wg    = (const float*)d_in[5];
    const float* out_w = (const float*)d_in[6];
    const float* out_b = (const float*)d_in[7];
    const float* ln_g  = (const float*)d_in[8];
    const float* ln_b  = (const float*)d_in[9];
    const float* lnr_g = (const float*)d_in[10];
    const float* lnr_b = (const float*)d_in[11];
    const float* lno_g = (const float*)d_in[12];
    const float* lno_b = (const float*)d_in[13];
    float* out = (float*)d_out;

    float *pxn, *pq, *pk, *pv, *pg, *po, *patt, *pcat, *ptmp;
    cudaGetSymbolAddress((void**)&pxn, g_xnorm);
    cudaGetSymbolAddress((void**)&pq, g_q);
    cudaGetSymbolAddress((void**)&pk, g_k);
    cudaGetSymbolAddress((void**)&pv, g_v);
    cudaGetSymbolAddress((void**)&pg, g_gt);
    cudaGetSymbolAddress((void**)&po, g_o);
    cudaGetSymbolAddress((void**)&patt, g_att);
    cudaGetSymbolAddress((void**)&pcat, g_cat);
    cudaGetSymbolAddress((void**)&ptmp, g_tmp);

    const int Mtot = Bb * Nn_SEQ;                       // 8192
    const long long nd = (long long)Nn_SEQ * Dd;        // 262144
    const long long nn = (long long)Nn_SEQ * Nn_SEQ;    // 1048576

    // 1) LN(x)
    ln_x_kernel<<<Mtot, 256>>>(x, ln_g, ln_b);

    // 2) Q/K/V/G projections: C[h] = x_norm @ W[h]   (M=8192, N=256, K=256)
    {
        dim3 grid(Dd / BN, Mtot / BM, Hh);              // (2, 64, 4)
        sgemm_kernel<<<grid, 256>>>(pxn, wq, pq, Mtot, Dd, Dd, 1.0f, 0,
                                    0LL, (long long)Dd * Dd, (long long)Bb * nd);
        sgemm_kernel<<<grid, 256>>>(pxn, wk, pk, Mtot, Dd, Dd, 1.0f, 0,
                                    0LL, (long long)Dd * Dd, (long long)Bb * nd);
        sgemm_kernel<<<grid, 256>>>(pxn, wv, pv, Mtot, Dd, Dd, 1.0f, 0,
                                    0LL, (long long)Dd * Dd, (long long)Bb * nd);
        sgemm_kernel<<<grid, 256>>>(pxn, wg, pg, Mtot, Dd, Dd, 1.0f, 0,
                                    0LL, (long long)Dd * Dd, (long long)Bb * nd);
    }

    // 3) scores: att[z] = scale * q[z] @ k[z]^T   (z = h*B+b; M=N=1024, K=256)
    {
        dim3 grid(Nn_SEQ / BN, Nn_SEQ / BM, Hh * Bb);   // (8, 8, 32)
        sgemm_kernel<<<grid, 256>>>(pq, pk, patt, Nn_SEQ, Nn_SEQ, Dd,
                                    0.0625f, 1, nd, nd, nn);
    }

    // 4) masked softmax
    softmax_kernel<<<Hh * Bb * Nn_SEQ, 256>>>(mask);

    // 5) out = att @ v   (M=1024, N=256, K=1024)
    {
        dim3 grid(Dd / BN, Nn_SEQ / BM, Hh * Bb);       // (2, 8, 32)
        sgemm_kernel<<<grid, 256>>>(patt, pv, po, Nn_SEQ, Dd, Nn_SEQ,
                                    1.0f, 0, nn, nd, nd);
    }

    // 6) gate + residual + LN(lnr) + scatter to concat
    gate_res_ln_kernel<<<Hh * Bb * Nn_SEQ, 256>>>(x, lnr_g, lnr_b);

    // 7) out projection: tmp = cat @ out_w   (M=8192, N=256, K=1024)
    {
        dim3 grid(Dd / BN, Mtot / BM, 1);               // (2, 64, 1)
        sgemm_kernel<<<grid, 256>>>(pcat, out_w, ptmp, Mtot, Dd, Dd * Hh,
                                    1.0f, 0, 0LL, 0LL, 0LL);
    }

    // 8) + bias + x, LN(lno), * mask
    final_kernel<<<Mtot, 256>>>(x, out_b, lno_g, lno_b, mask, out);
}

// round 6
// speedup vs baseline: 2.0762x; 2.0762x over previous
#include <cuda_runtime.h>
#include <mma.h>
#include <cstdint>
#include <math.h>

using namespace nvcuda;

// Problem dims
#define Bb 8
#define Nn_SEQ 1024
#define Dd 256
#define Hh 4
#define EPSF 1e-6f

// ---------------- scratch (device globals; no allocation allowed) ----------
__device__ float g_xnorm[Bb * Nn_SEQ * Dd];                   // 8 MB
__device__ float g_q[Hh * Bb * Nn_SEQ * Dd];                  // 32 MB
__device__ float g_k[Hh * Bb * Nn_SEQ * Dd];                  // 32 MB
__device__ float g_gt[Hh * Bb * Nn_SEQ * Dd];                 // 32 MB
__device__ float g_vt[Hh * Dd * Bb * Nn_SEQ];                 // 32 MB  [h][e][b*N+n]
__device__ float g_o[Hh * Bb * Nn_SEQ * Dd];                  // 32 MB
__device__ float g_att[(long long)Hh * Bb * Nn_SEQ * Nn_SEQ]; // 128 MB
__device__ float g_cat[Bb * Nn_SEQ * Dd * Hh];                // 32 MB
__device__ float g_tmp[Bb * Nn_SEQ * Dd];                     // 8 MB
__device__ float g_wqt[Hh * Dd * Dd];
__device__ float g_wkt[Hh * Dd * Dd];
__device__ float g_wvt[Hh * Dd * Dd];
__device__ float g_wgt[Hh * Dd * Dd];
__device__ float g_owt[Dd * Dd * Hh];                         // [256][1024]

// ======================= TF32 WMMA GEMM ====================================
// C[M, N] = alpha * A[M, K] @ B[N, K]^T   (A, B K-major row layouts)
// BM=BN=128, BK=32. 256 threads = 8 warps (2 x 4), warp tile 64 x 32
// (4 x 2 wmma 16x16x8 tiles). Single smem buffer + register double-buffer.
#define BM 128
#define BN 128
#define BK 32
#define PAD 36

__global__ void __launch_bounds__(256)
tf32_gemm_kernel(const float* __restrict__ A, const float* __restrict__ B,
                 float* __restrict__ C, int K, int lda, int ldb, int ldc,
                 long long bsA, long long bsB1, long long bsB2, int zdivB,
                 long long bsC, float alpha) {
    __shared__ float sA[BM][PAD];
    __shared__ float sB[BN][PAD];

    int tid = threadIdx.x, wid = tid >> 5;
    int z = blockIdx.z;
    A += (long long)z * bsA;
    B += (long long)(z / zdivB) * bsB1 + (long long)(z % zdivB) * bsB2;
    C += (long long)z * bsC;
    int m0 = blockIdx.y * BM;
    int n0 = blockIdx.x * BN;

    int warp_m = (wid & 1) * 64;      // 2 warps along M, 4 tiles of 16
    int warp_n = (wid >> 1) * 32;     // 4 warps along N, 2 tiles of 16

    wmma::fragment<wmma::accumulator, 16, 16, 8, float> acc[4][2];
#pragma unroll
    for (int mt = 0; mt < 4; ++mt)
#pragma unroll
        for (int nt = 0; nt < 2; ++nt)
            wmma::fill_fragment(acc[mt][nt], 0.0f);

    // staging addressing: 128 rows x 32 cols = 1024 float4 per matrix,
    // 4 float4 per thread per matrix. row = idx>>3, col4 = idx&7.
    int nchunks = K / BK;

    float4 ra[4], rb[4];
    // preload chunk 0
#pragma unroll
    for (int i = 0; i < 4; ++i) {
        int idx = tid + 256 * i;
        int r = idx >> 3, c4 = (idx & 7) * 4;
        ra[i] = *reinterpret_cast<const float4*>(A + (long long)(m0 + r) * lda + c4);
        rb[i] = *reinterpret_cast<const float4*>(B + (long long)(n0 + r) * ldb + c4);
    }

    for (int c = 0; c < nchunks; ++c) {
        // store staged regs to smem (convert to tf32 values here)
#pragma unroll
        for (int i = 0; i < 4; ++i) {
            int idx = tid + 256 * i;
            int r = idx >> 3, c4 = (idx & 7) * 4;
            float4 v = ra[i];
            float* d = &sA[r][c4];
            d[0] = wmma::__float_to_tf32(v.x);
            d[1] = wmma::__float_to_tf32(v.y);
            d[2] = wmma::__float_to_tf32(v.z);
            d[3] = wmma::__float_to_tf32(v.w);
            float4 w = rb[i];
            float* e = &sB[r][c4];
            e[0] = wmma::__float_to_tf32(w.x);
            e[1] = wmma::__float_to_tf32(w.y);
            e[2] = wmma::__float_to_tf32(w.z);
            e[3] = wmma::__float_to_tf32(w.w);
        }
        __syncthreads();

        // issue next chunk's global loads early
        if (c + 1 < nchunks) {
            int k0 = (c + 1) * BK;
#pragma unroll
            for (int i = 0; i < 4; ++i) {
                int idx = tid + 256 * i;
                int r = idx >> 3, c4 = (idx & 7) * 4;
                ra[i] = *reinterpret_cast<const float4*>(
                    A + (long long)(m0 + r) * lda + k0 + c4);
                rb[i] = *reinterpret_cast<const float4*>(
                    B + (long long)(n0 + r) * ldb + k0 + c4);
            }
        }

        // compute 4 k-steps of 8
#pragma unroll
        for (int ks = 0; ks < 4; ++ks) {
            wmma::fragment<wmma::matrix_a, 16, 16, 8, wmma::precision::tf32,
                           wmma::row_major> fa[4];
            wmma::fragment<wmma::matrix_b, 16, 16, 8, wmma::precision::tf32,
                           wmma::col_major> fb[2];
#pragma unroll
            for (int mt = 0; mt < 4; ++mt)
                wmma::load_matrix_sync(fa[mt], &sA[warp_m + mt * 16][ks * 8], PAD);
#pragma unroll
            for (int nt = 0; nt < 2; ++nt)
                wmma::load_matrix_sync(fb[nt], &sB[warp_n + nt * 16][ks * 8], PAD);
#pragma unroll
            for (int mt = 0; mt < 4; ++mt)
#pragma unroll
                for (int nt = 0; nt < 2; ++nt)
                    wmma::mma_sync(acc[mt][nt], fa[mt], fb[nt], acc[mt][nt]);
        }
        __syncthreads();
    }

    // epilogue
#pragma unroll
    for (int mt = 0; mt < 4; ++mt) {
#pragma unroll
        for (int nt = 0; nt < 2; ++nt) {
#pragma unroll
            for (int e = 0; e < acc[mt][nt].num_elements; ++e)
                acc[mt][nt].x[e] *= alpha;
            float* cp = C + (long long)(m0 + warp_m + mt * 16) * ldc
                          + (n0 + warp_n + nt * 16);
            wmma::store_matrix_sync(cp, acc[mt][nt], ldc, wmma::mem_row_major);
        }
    }
}

// ======================= transpose (for weight matrices) ===================
__global__ void transpose_kernel(const float* __restrict__ in, float* __restrict__ out,
                                 int R, int C) {
    __shared__ float t[32][33];
    long long zo = (long long)blockIdx.z * R * C;
    in += zo; out += zo;
    int c0 = blockIdx.x * 32, r0 = blockIdx.y * 32;
    int x = threadIdx.x, y = threadIdx.y;
#pragma unroll
    for (int i = 0; i < 32; i += 8)
        t[y + i][x] = in[(long long)(r0 + y + i) * C + c0 + x];
    __syncthreads();
#pragma unroll
    for (int i = 0; i < 32; i += 8)
        out[(long long)(c0 + y + i) * R + r0 + x] = t[x][y + i];
}

// ======================= reductions (blocks of 256) ========================
__device__ __forceinline__ float warpSum(float v) {
    v += __shfl_down_sync(0xffffffffu, v, 16);
    v += __shfl_down_sync(0xffffffffu, v, 8);
    v += __shfl_down_sync(0xffffffffu, v, 4);
    v += __shfl_down_sync(0xffffffffu, v, 2);
    v += __shfl_down_sync(0xffffffffu, v, 1);
    return v;
}
__device__ __forceinline__ float warpMax(float v) {
    v = fmaxf(v, __shfl_down_sync(0xffffffffu, v, 16));
    v = fmaxf(v, __shfl_down_sync(0xffffffffu, v, 8));
    v = fmaxf(v, __shfl_down_sync(0xffffffffu, v, 4));
    v = fmaxf(v, __shfl_down_sync(0xffffffffu, v, 2));
    v = fmaxf(v, __shfl_down_sync(0xffffffffu, v, 1));
    return v;
}
__device__ float blockSum256(float v) {
    __shared__ float s[8];
    int w = threadIdx.x >> 5, l = threadIdx.x & 31;
    v = warpSum(v);
    if (l == 0) s[w] = v;
    __syncthreads();
    if (w == 0) {
        float t = (l < 8) ? s[l] : 0.f;
        t = warpSum(t);
        if (l == 0) s[0] = t;
    }
    __syncthreads();
    float r = s[0];
    __syncthreads();
    return r;
}
__device__ float blockMax256(float v) {
    __shared__ float s[8];
    int w = threadIdx.x >> 5, l = threadIdx.x & 31;
    v = warpMax(v);
    if (l == 0) s[w] = v;
    __syncthreads();
    if (w == 0) {
        float t = (l < 8) ? s[l] : -3.4e38f;
        t = warpMax(t);
        if (l == 0) s[0] = t;
    }
    __syncthreads();
    float r = s[0];
    __syncthreads();
    return r;
}

// ======================= elementwise kernels ===============================
__global__ void ln_x_kernel(const float* __restrict__ x,
                            const float* __restrict__ g, const float* __restrict__ b) {
    long long row = blockIdx.x;
    int t = threadIdx.x;
    float v = x[row * Dd + t];
    float mean = blockSum256(v) * (1.0f / Dd);
    float d = v - mean;
    float var = blockSum256(d * d) * (1.0f / Dd);
    g_xnorm[row * Dd + t] = d * rsqrtf(var + EPSF) * g[t] + b[t];
}

__global__ void softmax_kernel(const int* __restrict__ mask) {
    int r = blockIdx.x;                       // (h*B + b)*N + n
    int n = r & (Nn_SEQ - 1);
    int hb = r >> 10;
    int b = hb & (Bb - 1);
    float* row = g_att + (long long)r * Nn_SEQ;
    int t = threadIdx.x;

    int mn = mask[b * Nn_SEQ + n];
    float s[4];
    int am[4];
    float mx = -3.4e38f;
#pragma unroll
    for (int i = 0; i < 4; ++i) {
        int idx = t + 256 * i;
        int mm = mask[b * Nn_SEQ + idx];
        am[i] = mn * mm;
        float v = row[idx];
        v = v + (1.0f - (float)am[i]) * (-1e9f);
        s[i] = v;
        mx = fmaxf(mx, v);
    }
    mx = blockMax256(mx);
    float lsum = 0.f;
#pragma unroll
    for (int i = 0; i < 4; ++i) {
        s[i] = expf(s[i] - mx);
        lsum += s[i];
    }
    float tot = blockSum256(lsum);
    float inv = 1.0f / tot;
#pragma unroll
    for (int i = 0; i < 4; ++i) {
        int idx = t + 256 * i;
        row[idx] = am[i] ? s[i] * inv : 0.0f;
    }
}

__global__ void gate_res_ln_kernel(const float* __restrict__ x,
                                   const float* __restrict__ lg,
                                   const float* __restrict__ lb) {
    int r = blockIdx.x;                       // (h*B + b)*N + n
    int t = threadIdx.x;
    int n = r & (Nn_SEQ - 1);
    int hb = r >> 10;
    int b = hb & (Bb - 1);
    int h = hb >> 3;
    long long idx = (long long)r * Dd + t;
    long long xrow = (long long)(b * Nn_SEQ + n) * Dd;

    float gv = g_gt[idx];
    float sig = 1.0f / (1.0f + expf(-gv));
    float val = g_o[idx] * sig + x[xrow + t];

    float mean = blockSum256(val) * (1.0f / Dd);
    float d = val - mean;
    float var = blockSum256(d * d) * (1.0f / Dd);
    float res = d * rsqrtf(var + EPSF) * lg[t] + lb[t];

    g_cat[(long long)(b * Nn_SEQ + n) * (Dd * Hh) + t * Hh + h] = res;
}

__global__ void final_kernel(const float* __restrict__ x,
                             const float* __restrict__ ob,
                             const float* __restrict__ lg,
                             const float* __restrict__ lb,
                             const int* __restrict__ mask,
                             float* __restrict__ out) {
    int r = blockIdx.x;                       // b*N + n
    int t = threadIdx.x;
    long long idx = (long long)r * Dd + t;
    float val = g_tmp[idx] + ob[t] + x[idx];
    float mean = blockSum256(val) * (1.0f / Dd);
    float d = val - mean;
    float var = blockSum256(d * d) * (1.0f / Dd);
    float res = d * rsqrtf(var + EPSF) * lg[t] + lb[t];
    out[idx] = res * (float)mask[r];
}

// ======================= launch ============================================
extern "C" void kernel_launch(void* const* d_in, const int* in_sizes, int n_in,
                              void* d_out, int out_size) {
    const float* x     = (const float*)d_in[0];
    const int*   mask  = (const int*)d_in[1];
    const float* wq    = (const float*)d_in[2];
    const float* wk    = (const float*)d_in[3];
    const float* wv    = (const float*)d_in[4];
    const float* wg    = (const float*)d_in[5];
    const float* out_w = (const float*)d_in[6];
    const float* out_b = (const float*)d_in[7];
    const float* ln_g  = (const float*)d_in[8];
    const float* ln_b  = (const float*)d_in[9];
    const float* lnr_g = (const float*)d_in[10];
    const float* lnr_b = (const float*)d_in[11];
    const float* lno_g = (const float*)d_in[12];
    const float* lno_b = (const float*)d_in[13];
    float* out = (float*)d_out;

    float *pxn, *pq, *pk, *pg, *pvt, *po, *patt, *pcat, *ptmp;
    float *pwqt, *pwkt, *pwvt, *pwgt, *powt;
    cudaGetSymbolAddress((void**)&pxn, g_xnorm);
    cudaGetSymbolAddress((void**)&pq, g_q);
    cudaGetSymbolAddress((void**)&pk, g_k);
    cudaGetSymbolAddress((void**)&pg, g_gt);
    cudaGetSymbolAddress((void**)&pvt, g_vt);
    cudaGetSymbolAddress((void**)&po, g_o);
    cudaGetSymbolAddress((void**)&patt, g_att);
    cudaGetSymbolAddress((void**)&pcat, g_cat);
    cudaGetSymbolAddress((void**)&ptmp, g_tmp);
    cudaGetSymbolAddress((void**)&pwqt, g_wqt);
    cudaGetSymbolAddress((void**)&pwkt, g_wkt);
    cudaGetSymbolAddress((void**)&pwvt, g_wvt);
    cudaGetSymbolAddress((void**)&pwgt, g_wgt);
    cudaGetSymbolAddress((void**)&powt, g_owt);

    const int Mtot = Bb * Nn_SEQ;                        // 8192
    const long long nd = (long long)Nn_SEQ * Dd;         // 262144
    const long long nn = (long long)Nn_SEQ * Nn_SEQ;     // 1048576
    const long long wsz = (long long)Dd * Dd;            // 65536

    // 0) weight transposes (W[K,N] -> W^T[N,K])
    {
        dim3 tb(32, 8);
        transpose_kernel<<<dim3(Dd / 32, Dd / 32, Hh), tb>>>(wq, pwqt, Dd, Dd);
        transpose_kernel<<<dim3(Dd / 32, Dd / 32, Hh), tb>>>(wk, pwkt, Dd, Dd);
        transpose_kernel<<<dim3(Dd / 32, Dd / 32, Hh), tb>>>(wv, pwvt, Dd, Dd);
        transpose_kernel<<<dim3(Dd / 32, Dd / 32, Hh), tb>>>(wg, pwgt, Dd, Dd);
        transpose_kernel<<<dim3(Dd / 32, (Dd * Hh) / 32, 1), tb>>>(out_w, powt, Dd * Hh, Dd);
    }

    // 1) LN(x)
    ln_x_kernel<<<Mtot, 256>>>(x, ln_g, ln_b);

    // 2) q/k/gate projections: C[h] = x_norm @ W[h]  (M=8192, N=256, K=256)
    tf32_gemm_kernel<<<dim3(Dd / BN, Mtot / BM, 4), 256>>>(
        pxn, pwqt, pq, Dd, Dd, Dd, Dd, 0LL, wsz, 0LL, 1, (long long)Mtot * Dd, 1.0f);
    tf32_gemm_kernel<<<dim3(Dd / BN, Mtot / BM, 4), 256>>>(
        pxn, pwkt, pk, Dd, Dd, Dd, Dd, 0LL, wsz, 0LL, 1, (long long)Mtot * Dd, 1.0f);
    tf32_gemm_kernel<<<dim3(Dd / BN, Mtot / BM, 4), 256>>>(
        pxn, pwgt, pg, Dd, Dd, Dd, Dd, 0LL, wsz, 0LL, 1, (long long)Mtot * Dd, 1.0f);

    // 2b) v transposed: vt[h][e][bn] = sum_d wv[h][d][e] * x_norm[bn][d]
    //     A = wv^T [256,256], B = x_norm [8192,256], C = vt [256, 8192]
    tf32_gemm_kernel<<<dim3(Mtot / BN, Dd / BM, 4), 256>>>(
        pwvt, pxn, pvt, Dd, Dd, Dd, Mtot, wsz, 0LL, 0LL, 1, (long long)Dd * Mtot, 1.0f);

    // 3) scores: att[z] = (1/16) q[z] @ k[z]^T  (z=h*B+b; M=N=1024, K=256)
    tf32_gemm_kernel<<<dim3(Nn_SEQ / BN, Nn_SEQ / BM, Hh * Bb), 256>>>(
        pq, pk, patt, Dd, Dd, Dd, Nn_SEQ, nd, nd, 0LL, 1, nn, 0.0625f);

    // 4) masked softmax
    softmax_kernel<<<Hh * Bb * Nn_SEQ, 256>>>(mask);

    // 5) out = att @ v  (B-operand = vt slice: [256, 1024] with row stride 8192)
    tf32_gemm_kernel<<<dim3(Dd / BN, Nn_SEQ / BM, Hh * Bb), 256>>>(
        patt, pvt, po, Nn_SEQ, Nn_SEQ, Mtot, Dd,
        nn, (long long)Dd * Mtot, (long long)Nn_SEQ, Bb, nd, 1.0f);

    // 6) gate + residual + LN(lnr) + scatter to concat
    gate_res_ln_kernel<<<Hh * Bb * Nn_SEQ, 256>>>(x, lnr_g, lnr_b);

    // 7) out projection: tmp = cat @ out_w  (M=8192, N=256, K=1024)
    tf32_gemm_kernel<<<dim3(Dd / BN, Mtot / BM, 1), 256>>>(
        pcat, powt, ptmp, Dd * Hh, Dd * Hh, Dd * Hh, Dd,
        0LL, 0LL, 0LL, 1, 0LL, 1.0f);

    // 8) + bias + x, LN(lno), * mask
    final_kernel<<<Mtot, 256>>>(x, out_b, lno_g, lno_b, mask, out);
}

// round 7
// speedup vs baseline: 4.2984x; 2.0703x over previous
#include <cuda_runtime.h>
#include <mma.h>
#include <cuda_fp16.h>
#include <cstdint>
#include <math.h>

using namespace nvcuda;

// Problem dims
#define Bb 8
#define Nn_SEQ 1024
#define Dd 256
#define Hh 4
#define EPSF 1e-6f

// ---------------- scratch (device globals; no allocation allowed) ----------
__device__ float g_xnorm[Bb * Nn_SEQ * Dd];                   // 8 MB
__device__ float g_q[Hh * Bb * Nn_SEQ * Dd];                  // 32 MB
__device__ float g_k[Hh * Bb * Nn_SEQ * Dd];                  // 32 MB
__device__ float g_gt[Hh * Bb * Nn_SEQ * Dd];                 // 32 MB
__device__ float g_vt[Hh * Dd * Bb * Nn_SEQ];                 // 32 MB  [h][e][b*N+n]
__device__ float g_o[Hh * Bb * Nn_SEQ * Dd];                  // 32 MB
__device__ float g_att[(long long)Hh * Bb * Nn_SEQ * Nn_SEQ]; // 128 MB
__device__ float g_cat[Bb * Nn_SEQ * Dd * Hh];                // 32 MB
__device__ float g_tmp[Bb * Nn_SEQ * Dd];                     // 8 MB
__device__ float g_wqt[Hh * Dd * Dd];
__device__ float g_wkt[Hh * Dd * Dd];
__device__ float g_wvt[Hh * Dd * Dd];
__device__ float g_wgt[Hh * Dd * Dd];
__device__ float g_owt[Dd * Dd * Hh];                         // [256][1024]

// ======================= FP16 WMMA GEMM ====================================
// C[M, N] = alpha * A[M, K] @ B[N, K]^T   (A, B fp32 K-major row layouts;
// converted to fp16 at smem staging; fp32 accumulate).
// BM=BN=128, BK=32. 256 threads = 8 warps (2 x 4), warp tile 64 x 32
// (4 x 2 wmma 16x16x16 tiles). Double-buffered smem, 1 sync per chunk.
#define BM 128
#define BN 128
#define BK 32
#define PADH 40   // halves per row (32 data + 8 pad) = 80 B

__global__ void __launch_bounds__(256)
fp16_gemm_kernel(const float* __restrict__ A, const float* __restrict__ B,
                 float* __restrict__ C, int K, int lda, int ldb, int ldc,
                 long long bsA, long long bsB1, long long bsB2, int zdivB,
                 long long bsC, float alpha) {
    __shared__ __half sA[2][BM][PADH];
    __shared__ __half sB[2][BN][PADH];

    int tid = threadIdx.x, wid = tid >> 5;
    int z = blockIdx.z;
    A += (long long)z * bsA;
    B += (long long)(z / zdivB) * bsB1 + (long long)(z % zdivB) * bsB2;
    C += (long long)z * bsC;
    int m0 = blockIdx.y * BM;
    int n0 = blockIdx.x * BN;

    int warp_m = (wid & 1) * 64;      // 2 warps along M, 4 tiles of 16
    int warp_n = (wid >> 1) * 32;     // 4 warps along N, 2 tiles of 16

    wmma::fragment<wmma::accumulator, 16, 16, 16, float> acc[4][2];
#pragma unroll
    for (int mt = 0; mt < 4; ++mt)
#pragma unroll
        for (int nt = 0; nt < 2; ++nt)
            wmma::fill_fragment(acc[mt][nt], 0.0f);

    // staging: 128 rows x 32 cols fp32 per matrix = 4 float4/thread/matrix
    int nchunks = K / BK;

    float4 ra[4], rb[4];
    auto load_chunk = [&](int k0) {
#pragma unroll
        for (int i = 0; i < 4; ++i) {
            int idx = tid + 256 * i;
            int r = idx >> 3, c4 = (idx & 7) * 4;
            ra[i] = *reinterpret_cast<const float4*>(
                A + (long long)(m0 + r) * lda + k0 + c4);
            rb[i] = *reinterpret_cast<const float4*>(
                B + (long long)(n0 + r) * ldb + k0 + c4);
        }
    };
    auto store_chunk = [&](int s) {
#pragma unroll
        for (int i = 0; i < 4; ++i) {
            int idx = tid + 256 * i;
            int r = idx >> 3, c4 = (idx & 7) * 4;
            __half2* d = reinterpret_cast<__half2*>(&sA[s][r][c4]);
            d[0] = __floats2half2_rn(ra[i].x, ra[i].y);
            d[1] = __floats2half2_rn(ra[i].z, ra[i].w);
            __half2* e = reinterpret_cast<__half2*>(&sB[s][r][c4]);
            e[0] = __floats2half2_rn(rb[i].x, rb[i].y);
            e[1] = __floats2half2_rn(rb[i].z, rb[i].w);
        }
    };

    load_chunk(0);
    store_chunk(0);
    __syncthreads();

    for (int c = 0; c < nchunks; ++c) {
        int s = c & 1;
        if (c + 1 < nchunks)
            load_chunk((c + 1) * BK);      // global loads overlap compute

        // compute 2 k-steps of 16 from buffer s
#pragma unroll
        for (int ks = 0; ks < 2; ++ks) {
            wmma::fragment<wmma::matrix_a, 16, 16, 16, __half, wmma::row_major> fa[4];
            wmma::fragment<wmma::matrix_b, 16, 16, 16, __half, wmma::col_major> fb[2];
#pragma unroll
            for (int mt = 0; mt < 4; ++mt)
                wmma::load_matrix_sync(fa[mt], &sA[s][warp_m + mt * 16][ks * 16], PADH);
#pragma unroll
            for (int nt = 0; nt < 2; ++nt)
                wmma::load_matrix_sync(fb[nt], &sB[s][warp_n + nt * 16][ks * 16], PADH);
#pragma unroll
            for (int mt = 0; mt < 4; ++mt)
#pragma unroll
                for (int nt = 0; nt < 2; ++nt)
                    wmma::mma_sync(acc[mt][nt], fa[mt], fb[nt], acc[mt][nt]);
        }

        if (c + 1 < nchunks) {
            store_chunk(1 - s);            // fill the other buffer
            __syncthreads();               // single barrier per chunk
        }
    }

    // epilogue
#pragma unroll
    for (int mt = 0; mt < 4; ++mt) {
#pragma unroll
        for (int nt = 0; nt < 2; ++nt) {
#pragma unroll
            for (int e = 0; e < acc[mt][nt].num_elements; ++e)
                acc[mt][nt].x[e] *= alpha;
            float* cp = C + (long long)(m0 + warp_m + mt * 16) * ldc
                          + (n0 + warp_n + nt * 16);
            wmma::store_matrix_sync(cp, acc[mt][nt], ldc, wmma::mem_row_major);
        }
    }
}

// ======================= transpose (for weight matrices) ===================
__global__ void transpose_kernel(const float* __restrict__ in, float* __restrict__ out,
                                 int R, int C) {
    __shared__ float t[32][33];
    long long zo = (long long)blockIdx.z * R * C;
    in += zo; out += zo;
    int c0 = blockIdx.x * 32, r0 = blockIdx.y * 32;
    int x = threadIdx.x, y = threadIdx.y;
#pragma unroll
    for (int i = 0; i < 32; i += 8)
        t[y + i][x] = in[(long long)(r0 + y + i) * C + c0 + x];
    __syncthreads();
#pragma unroll
    for (int i = 0; i < 32; i += 8)
        out[(long long)(c0 + y + i) * R + r0 + x] = t[x][y + i];
}

// ======================= reductions (blocks of 256) ========================
__device__ __forceinline__ float warpSum(float v) {
    v += __shfl_down_sync(0xffffffffu, v, 16);
    v += __shfl_down_sync(0xffffffffu, v, 8);
    v += __shfl_down_sync(0xffffffffu, v, 4);
    v += __shfl_down_sync(0xffffffffu, v, 2);
    v += __shfl_down_sync(0xffffffffu, v, 1);
    return v;
}
__device__ __forceinline__ float warpMax(float v) {
    v = fmaxf(v, __shfl_down_sync(0xffffffffu, v, 16));
    v = fmaxf(v, __shfl_down_sync(0xffffffffu, v, 8));
    v = fmaxf(v, __shfl_down_sync(0xffffffffu, v, 4));
    v = fmaxf(v, __shfl_down_sync(0xffffffffu, v, 2));
    v = fmaxf(v, __shfl_down_sync(0xffffffffu, v, 1));
    return v;
}
__device__ float blockSum256(float v) {
    __shared__ float s[8];
    int w = threadIdx.x >> 5, l = threadIdx.x & 31;
    v = warpSum(v);
    if (l == 0) s[w] = v;
    __syncthreads();
    if (w == 0) {
        float t = (l < 8) ? s[l] : 0.f;
        t = warpSum(t);
        if (l == 0) s[0] = t;
    }
    __syncthreads();
    float r = s[0];
    __syncthreads();
    return r;
}
__device__ float blockMax256(float v) {
    __shared__ float s[8];
    int w = threadIdx.x >> 5, l = threadIdx.x & 31;
    v = warpMax(v);
    if (l == 0) s[w] = v;
    __syncthreads();
    if (w == 0) {
        float t = (l < 8) ? s[l] : -3.4e38f;
        t = warpMax(t);
        if (l == 0) s[0] = t;
    }
    __syncthreads();
    float r = s[0];
    __syncthreads();
    return r;
}

// ======================= elementwise kernels ===============================
__global__ void ln_x_kernel(const float* __restrict__ x,
                            const float* __restrict__ g, const float* __restrict__ b) {
    long long row = blockIdx.x;
    int t = threadIdx.x;
    float v = x[row * Dd + t];
    float mean = blockSum256(v) * (1.0f / Dd);
    float d = v - mean;
    float var = blockSum256(d * d) * (1.0f / Dd);
    g_xnorm[row * Dd + t] = d * rsqrtf(var + EPSF) * g[t] + b[t];
}

__global__ void softmax_kernel(const int* __restrict__ mask) {
    int r = blockIdx.x;                       // (h*B + b)*N + n
    int n = r & (Nn_SEQ - 1);
    int hb = r >> 10;
    int b = hb & (Bb - 1);
    float* row = g_att + (long long)r * Nn_SEQ;
    int t = threadIdx.x;

    int mn = mask[b * Nn_SEQ + n];
    float s[4];
    int am[4];
    float mx = -3.4e38f;
#pragma unroll
    for (int i = 0; i < 4; ++i) {
        int idx = t + 256 * i;
        int mm = mask[b * Nn_SEQ + idx];
        am[i] = mn * mm;
        float v = row[idx];
        v = v + (1.0f - (float)am[i]) * (-1e9f);
        s[i] = v;
        mx = fmaxf(mx, v);
    }
    mx = blockMax256(mx);
    float lsum = 0.f;
#pragma unroll
    for (int i = 0; i < 4; ++i) {
        s[i] = expf(s[i] - mx);
        lsum += s[i];
    }
    float tot = blockSum256(lsum);
    float inv = 1.0f / tot;
#pragma unroll
    for (int i = 0; i < 4; ++i) {
        int idx = t + 256 * i;
        row[idx] = am[i] ? s[i] * inv : 0.0f;
    }
}

__global__ void gate_res_ln_kernel(const float* __restrict__ x,
                                   const float* __restrict__ lg,
                                   const float* __restrict__ lb) {
    int r = blockIdx.x;                       // (h*B + b)*N + n
    int t = threadIdx.x;
    int n = r & (Nn_SEQ - 1);
    int hb = r >> 10;
    int b = hb & (Bb - 1);
    int h = hb >> 3;
    long long idx = (long long)r * Dd + t;
    long long xrow = (long long)(b * Nn_SEQ + n) * Dd;

    float gv = g_gt[idx];
    float sig = 1.0f / (1.0f + expf(-gv));
    float val = g_o[idx] * sig + x[xrow + t];

    float mean = blockSum256(val) * (1.0f / Dd);
    float d = val - mean;
    float var = blockSum256(d * d) * (1.0f / Dd);
    float res = d * rsqrtf(var + EPSF) * lg[t] + lb[t];

    g_cat[(long long)(b * Nn_SEQ + n) * (Dd * Hh) + t * Hh + h] = res;
}

__global__ void final_kernel(const float* __restrict__ x,
                             const float* __restrict__ ob,
                             const float* __restrict__ lg,
                             const float* __restrict__ lb,
                             const int* __restrict__ mask,
                             float* __restrict__ out) {
    int r = blockIdx.x;                       // b*N + n
    int t = threadIdx.x;
    long long idx = (long long)r * Dd + t;
    float val = g_tmp[idx] + ob[t] + x[idx];
    float mean = blockSum256(val) * (1.0f / Dd);
    float d = val - mean;
    float var = blockSum256(d * d) * (1.0f / Dd);
    float res = d * rsqrtf(var + EPSF) * lg[t] + lb[t];
    out[idx] = res * (float)mask[r];
}

// ======================= launch ============================================
extern "C" void kernel_launch(void* const* d_in, const int* in_sizes, int n_in,
                              void* d_out, int out_size) {
    const float* x     = (const float*)d_in[0];
    const int*   mask  = (const int*)d_in[1];
    const float* wq    = (const float*)d_in[2];
    const float* wk    = (const float*)d_in[3];
    const float* wv    = (const float*)d_in[4];
    const float* wg    = (const float*)d_in[5];
    const float* out_w = (const float*)d_in[6];
    const float* out_b = (const float*)d_in[7];
    const float* ln_g  = (const float*)d_in[8];
    const float* ln_b  = (const float*)d_in[9];
    const float* lnr_g = (const float*)d_in[10];
    const float* lnr_b = (const float*)d_in[11];
    const float* lno_g = (const float*)d_in[12];
    const float* lno_b = (const float*)d_in[13];
    float* out = (float*)d_out;

    float *pxn, *pq, *pk, *pg, *pvt, *po, *patt, *pcat, *ptmp;
    float *pwqt, *pwkt, *pwvt, *pwgt, *powt;
    cudaGetSymbolAddress((void**)&pxn, g_xnorm);
    cudaGetSymbolAddress((void**)&pq, g_q);
    cudaGetSymbolAddress((void**)&pk, g_k);
    cudaGetSymbolAddress((void**)&pg, g_gt);
    cudaGetSymbolAddress((void**)&pvt, g_vt);
    cudaGetSymbolAddress((void**)&po, g_o);
    cudaGetSymbolAddress((void**)&patt, g_att);
    cudaGetSymbolAddress((void**)&pcat, g_cat);
    cudaGetSymbolAddress((void**)&ptmp, g_tmp);
    cudaGetSymbolAddress((void**)&pwqt, g_wqt);
    cudaGetSymbolAddress((void**)&pwkt, g_wkt);
    cudaGetSymbolAddress((void**)&pwvt, g_wvt);
    cudaGetSymbolAddress((void**)&pwgt, g_wgt);
    cudaGetSymbolAddress((void**)&powt, g_owt);

    const int Mtot = Bb * Nn_SEQ;                        // 8192
    const long long nd = (long long)Nn_SEQ * Dd;         // 262144
    const long long nn = (long long)Nn_SEQ * Nn_SEQ;     // 1048576
    const long long wsz = (long long)Dd * Dd;            // 65536

    // 0) weight transposes (W[K,N] -> W^T[N,K])
    {
        dim3 tb(32, 8);
        transpose_kernel<<<dim3(Dd / 32, Dd / 32, Hh), tb>>>(wq, pwqt, Dd, Dd);
        transpose_kernel<<<dim3(Dd / 32, Dd / 32, Hh), tb>>>(wk, pwkt, Dd, Dd);
        transpose_kernel<<<dim3(Dd / 32, Dd / 32, Hh), tb>>>(wv, pwvt, Dd, Dd);
        transpose_kernel<<<dim3(Dd / 32, Dd / 32, Hh), tb>>>(wg, pwgt, Dd, Dd);
        transpose_kernel<<<dim3(Dd / 32, (Dd * Hh) / 32, 1), tb>>>(out_w, powt, Dd * Hh, Dd);
    }

    // 1) LN(x)
    ln_x_kernel<<<Mtot, 256>>>(x, ln_g, ln_b);

    // 2) q/k/gate projections: C[h] = x_norm @ W[h]  (M=8192, N=256, K=256)
    fp16_gemm_kernel<<<dim3(Dd / BN, Mtot / BM, 4), 256>>>(
        pxn, pwqt, pq, Dd, Dd, Dd, Dd, 0LL, wsz, 0LL, 1, (long long)Mtot * Dd, 1.0f);
    fp16_gemm_kernel<<<dim3(Dd / BN, Mtot / BM, 4), 256>>>(
        pxn, pwkt, pk, Dd, Dd, Dd, Dd, 0LL, wsz, 0LL, 1, (long long)Mtot * Dd, 1.0f);
    fp16_gemm_kernel<<<dim3(Dd / BN, Mtot / BM, 4), 256>>>(
        pxn, pwgt, pg, Dd, Dd, Dd, Dd, 0LL, wsz, 0LL, 1, (long long)Mtot * Dd, 1.0f);

    // 2b) v transposed: vt[h][e][bn] = sum_d wv[h][d][e] * x_norm[bn][d]
    //     A = wv^T [256,256], B = x_norm [8192,256], C = vt [256, 8192]
    fp16_gemm_kernel<<<dim3(Mtot / BN, Dd / BM, 4), 256>>>(
        pwvt, pxn, pvt, Dd, Dd, Dd, Mtot, wsz, 0LL, 0LL, 1, (long long)Dd * Mtot, 1.0f);

    // 3) scores: att[z] = (1/16) q[z] @ k[z]^T  (z=h*B+b; M=N=1024, K=256)
    fp16_gemm_kernel<<<dim3(Nn_SEQ / BN, Nn_SEQ / BM, Hh * Bb), 256>>>(
        pq, pk, patt, Dd, Dd, Dd, Nn_SEQ, nd, nd, 0LL, 1, nn, 0.0625f);

    // 4) masked softmax
    softmax_kernel<<<Hh * Bb * Nn_SEQ, 256>>>(mask);

    // 5) out = att @ v  (B-operand = vt slice: [256, 1024] with row stride 8192)
    fp16_gemm_kernel<<<dim3(Dd / BN, Nn_SEQ / BM, Hh * Bb), 256>>>(
        patt, pvt, po, Nn_SEQ, Nn_SEQ, Mtot, Dd,
        nn, (long long)Dd * Mtot, (long long)Nn_SEQ, Bb, nd, 1.0f);

    // 6) gate + residual + LN(lnr) + scatter to concat
    gate_res_ln_kernel<<<Hh * Bb * Nn_SEQ, 256>>>(x, lnr_g, lnr_b);

    // 7) out projection: tmp = cat @ out_w  (M=8192, N=256, K=1024)
    fp16_gemm_kernel<<<dim3(Dd / BN, Mtot / BM, 1), 256>>>(
        pcat, powt, ptmp, Dd * Hh, Dd * Hh, Dd * Hh, Dd,
        0LL, 0LL, 0LL, 1, 0LL, 1.0f);

    // 8) + bias + x, LN(lno), * mask
    final_kernel<<<Mtot, 256>>>(x, out_b, lno_g, lno_b, mask, out);
}

// round 8
// speedup vs baseline: 5.5378x; 1.2883x over previous
#include <cuda_runtime.h>
#include <mma.h>
#include <cuda_fp16.h>
#include <cstdint>
#include <math.h>

using namespace nvcuda;

// Problem dims
#define Bb 8
#define Nn_SEQ 1024
#define Dd 256
#define Hh 4
#define EPSF 1e-6f

// ---------------- scratch (device globals; no allocation allowed) ----------
__device__ __align__(16) __half g_xnorm[Bb * Nn_SEQ * Dd];                 // 4 MB
__device__ __align__(16) __half g_q[Hh * Bb * Nn_SEQ * Dd];                // 16 MB
__device__ __align__(16) __half g_k[Hh * Bb * Nn_SEQ * Dd];                // 16 MB
__device__ __align__(16) __half g_gt[Hh * Bb * Nn_SEQ * Dd];               // 16 MB
__device__ __align__(16) __half g_vt[Hh * Dd * Bb * Nn_SEQ];               // 16 MB [h][e][b*N+n]
__device__ float g_o[Hh * Bb * Nn_SEQ * Dd];                               // 32 MB
__device__ float g_att[(long long)Hh * Bb * Nn_SEQ * Nn_SEQ];              // 128 MB (scores, fp32)
__device__ __align__(16) __half g_attp[(long long)Hh * Bb * Nn_SEQ * Nn_SEQ]; // 64 MB (probs, fp16)
__device__ __align__(16) __half g_cat[Bb * Nn_SEQ * Dd * Hh];              // 16 MB
__device__ float g_tmp[Bb * Nn_SEQ * Dd];                                  // 8 MB
__device__ __align__(16) __half g_wqt[Hh * Dd * Dd];
__device__ __align__(16) __half g_wkt[Hh * Dd * Dd];
__device__ __align__(16) __half g_wvt[Hh * Dd * Dd];
__device__ __align__(16) __half g_wgt[Hh * Dd * Dd];
__device__ __align__(16) __half g_owt[Dd * Dd * Hh];                       // [256][1024]

// ======================= FP16 WMMA GEMM ====================================
// C[M, N] = alpha * A[M, K] @ B[N, K]^T  (A, B fp16 K-major; fp32 accumulate;
// output fp32 or fp16 by template).
// BM=BN=128, BK=32. 256 threads = 8 warps (2 x 4), warp tile 64 x 32.
// Double-buffered smem, 1 sync per chunk; staging is pure 16B copies.
#define BM 128
#define BN 128
#define BK 32
#define PADH 40   // halves per row (32 data + 8 pad) = 80 B

template <bool OUTH>
__global__ void __launch_bounds__(256)
fp16_gemm_kernel(const __half* __restrict__ A, const __half* __restrict__ B,
                 void* __restrict__ Cv, int K, int lda, int ldb, int ldc,
                 long long bsA, long long bsB1, long long bsB2, int zdivB,
                 long long bsC, float alpha) {
    __shared__ __half sA[2][BM][PADH];
    __shared__ __half sB[2][BN][PADH];

    int tid = threadIdx.x, wid = tid >> 5, lane = tid & 31;
    int z = blockIdx.z;
    A += (long long)z * bsA;
    B += (long long)(z / zdivB) * bsB1 + (long long)(z % zdivB) * bsB2;
    int m0 = blockIdx.y * BM;
    int n0 = blockIdx.x * BN;

    int warp_m = (wid & 1) * 64;      // 2 warps along M, 4 tiles of 16
    int warp_n = (wid >> 1) * 32;     // 4 warps along N, 2 tiles of 16

    wmma::fragment<wmma::accumulator, 16, 16, 16, float> acc[4][2];
#pragma unroll
    for (int mt = 0; mt < 4; ++mt)
#pragma unroll
        for (int nt = 0; nt < 2; ++nt)
            wmma::fill_fragment(acc[mt][nt], 0.0f);

    // staging: 128 rows x 32 halves = 64 B/row -> 2 uint4/thread/matrix
    int nchunks = K / BK;

    uint4 ra[2], rb[2];
    auto load_chunk = [&](int k0) {
#pragma unroll
        for (int i = 0; i < 2; ++i) {
            int idx = tid + 256 * i;
            int r = idx >> 2, c8 = (idx & 3) * 8;
            ra[i] = *reinterpret_cast<const uint4*>(
                A + (long long)(m0 + r) * lda + k0 + c8);
            rb[i] = *reinterpret_cast<const uint4*>(
                B + (long long)(n0 + r) * ldb + k0 + c8);
        }
    };
    auto store_chunk = [&](int s) {
#pragma unroll
        for (int i = 0; i < 2; ++i) {
            int idx = tid + 256 * i;
            int r = idx >> 2, c8 = (idx & 3) * 8;
            *reinterpret_cast<uint4*>(&sA[s][r][c8]) = ra[i];
            *reinterpret_cast<uint4*>(&sB[s][r][c8]) = rb[i];
        }
    };

    load_chunk(0);
    store_chunk(0);
    __syncthreads();

    for (int c = 0; c < nchunks; ++c) {
        int s = c & 1;
        if (c + 1 < nchunks)
            load_chunk((c + 1) * BK);      // global loads overlap compute

#pragma unroll
        for (int ks = 0; ks < 2; ++ks) {
            wmma::fragment<wmma::matrix_a, 16, 16, 16, __half, wmma::row_major> fa[4];
            wmma::fragment<wmma::matrix_b, 16, 16, 16, __half, wmma::col_major> fb[2];
#pragma unroll
            for (int mt = 0; mt < 4; ++mt)
                wmma::load_matrix_sync(fa[mt], &sA[s][warp_m + mt * 16][ks * 16], PADH);
#pragma unroll
            for (int nt = 0; nt < 2; ++nt)
                wmma::load_matrix_sync(fb[nt], &sB[s][warp_n + nt * 16][ks * 16], PADH);
#pragma unroll
            for (int mt = 0; mt < 4; ++mt)
#pragma unroll
                for (int nt = 0; nt < 2; ++nt)
                    wmma::mma_sync(acc[mt][nt], fa[mt], fb[nt], acc[mt][nt]);
        }

        if (c + 1 < nchunks) {
            store_chunk(1 - s);            // fill the other buffer
            __syncthreads();               // single barrier per chunk
        }
    }

    // ---- epilogue --------------------------------------------------------
#pragma unroll
    for (int mt = 0; mt < 4; ++mt)
#pragma unroll
        for (int nt = 0; nt < 2; ++nt)
#pragma unroll
            for (int e = 0; e < acc[mt][nt].num_elements; ++e)
                acc[mt][nt].x[e] *= alpha;

    if (!OUTH) {
        float* C = (float*)Cv + (long long)z * bsC;
#pragma unroll
        for (int mt = 0; mt < 4; ++mt)
#pragma unroll
            for (int nt = 0; nt < 2; ++nt) {
                float* cp = C + (long long)(m0 + warp_m + mt * 16) * ldc
                              + (n0 + warp_n + nt * 16);
                wmma::store_matrix_sync(cp, acc[mt][nt], ldc, wmma::mem_row_major);
            }
    } else {
        __half* C = (__half*)Cv + (long long)z * bsC;
        __syncthreads();   // done with sA/sB; reuse as fp32 bounce buffers
        float* wstage = reinterpret_cast<float*>(&sA[0][0][0]) + wid * 256;
        int lrow = lane >> 1, lcol = (lane & 1) * 8;
#pragma unroll
        for (int mt = 0; mt < 4; ++mt)
#pragma unroll
            for (int nt = 0; nt < 2; ++nt) {
                wmma::store_matrix_sync(wstage, acc[mt][nt], 16, wmma::mem_row_major);
                __syncwarp();
                const float* src = wstage + lrow * 16 + lcol;
                uint2 o;
                __half2 h0 = __floats2half2_rn(src[0], src[1]);
                __half2 h1 = __floats2half2_rn(src[2], src[3]);
                __half2 h2 = __floats2half2_rn(src[4], src[5]);
                __half2 h3 = __floats2half2_rn(src[6], src[7]);
                uint4 pk;
                pk.x = *reinterpret_cast<uint32_t*>(&h0);
                pk.y = *reinterpret_cast<uint32_t*>(&h1);
                pk.z = *reinterpret_cast<uint32_t*>(&h2);
                pk.w = *reinterpret_cast<uint32_t*>(&h3);
                (void)o;
                __half* cp = C + (long long)(m0 + warp_m + mt * 16 + lrow) * ldc
                               + (n0 + warp_n + nt * 16 + lcol);
                *reinterpret_cast<uint4*>(cp) = pk;
                __syncwarp();
            }
    }
}

// ======================= transposes (weights -> fp16) ======================
__global__ void transpose_h_kernel(const float* __restrict__ in, __half* __restrict__ out,
                                   int R, int C) {
    __shared__ float t[32][33];
    long long zo = (long long)blockIdx.z * R * C;
    in += zo; out += zo;
    int c0 = blockIdx.x * 32, r0 = blockIdx.y * 32;
    int x = threadIdx.x, y = threadIdx.y;
#pragma unroll
    for (int i = 0; i < 32; i += 8)
        t[y + i][x] = in[(long long)(r0 + y + i) * C + c0 + x];
    __syncthreads();
#pragma unroll
    for (int i = 0; i < 32; i += 8)
        out[(long long)(c0 + y + i) * R + r0 + x] = __float2half_rn(t[x][y + i]);
}

// ======================= reductions (blocks of 256) ========================
__device__ __forceinline__ float warpSum(float v) {
    v += __shfl_down_sync(0xffffffffu, v, 16);
    v += __shfl_down_sync(0xffffffffu, v, 8);
    v += __shfl_down_sync(0xffffffffu, v, 4);
    v += __shfl_down_sync(0xffffffffu, v, 2);
    v += __shfl_down_sync(0xffffffffu, v, 1);
    return v;
}
__device__ __forceinline__ float warpMax(float v) {
    v = fmaxf(v, __shfl_down_sync(0xffffffffu, v, 16));
    v = fmaxf(v, __shfl_down_sync(0xffffffffu, v, 8));
    v = fmaxf(v, __shfl_down_sync(0xffffffffu, v, 4));
    v = fmaxf(v, __shfl_down_sync(0xffffffffu, v, 2));
    v = fmaxf(v, __shfl_down_sync(0xffffffffu, v, 1));
    return v;
}
__device__ float blockSum256(float v) {
    __shared__ float s[8];
    int w = threadIdx.x >> 5, l = threadIdx.x & 31;
    v = warpSum(v);
    if (l == 0) s[w] = v;
    __syncthreads();
    if (w == 0) {
        float t = (l < 8) ? s[l] : 0.f;
        t = warpSum(t);
        if (l == 0) s[0] = t;
    }
    __syncthreads();
    float r = s[0];
    __syncthreads();
    return r;
}
__device__ float blockMax256(float v) {
    __shared__ float s[8];
    int w = threadIdx.x >> 5, l = threadIdx.x & 31;
    v = warpMax(v);
    if (l == 0) s[w] = v;
    __syncthreads();
    if (w == 0) {
        float t = (l < 8) ? s[l] : -3.4e38f;
        t = warpMax(t);
        if (l == 0) s[0] = t;
    }
    __syncthreads();
    float r = s[0];
    __syncthreads();
    return r;
}

// ======================= elementwise kernels ===============================
__global__ void ln_x_kernel(const float* __restrict__ x,
                            const float* __restrict__ g, const float* __restrict__ b) {
    long long row = blockIdx.x;
    int t = threadIdx.x;
    float v = x[row * Dd + t];
    float mean = blockSum256(v) * (1.0f / Dd);
    float d = v - mean;
    float var = blockSum256(d * d) * (1.0f / Dd);
    g_xnorm[row * Dd + t] = __float2half_rn(d * rsqrtf(var + EPSF) * g[t] + b[t]);
}

__global__ void softmax_kernel(const int* __restrict__ mask) {
    int r = blockIdx.x;                       // (h*B + b)*N + n
    int n = r & (Nn_SEQ - 1);
    int hb = r >> 10;
    int b = hb & (Bb - 1);
    const float* row = g_att + (long long)r * Nn_SEQ;
    __half* prow = g_attp + (long long)r * Nn_SEQ;
    int t = threadIdx.x;

    int mn = mask[b * Nn_SEQ + n];
    float s[4];
    int am[4];
    float mx = -3.4e38f;
#pragma unroll
    for (int i = 0; i < 4; ++i) {
        int idx = t + 256 * i;
        int mm = mask[b * Nn_SEQ + idx];
        am[i] = mn * mm;
        float v = row[idx];
        v = v + (1.0f - (float)am[i]) * (-1e9f);
        s[i] = v;
        mx = fmaxf(mx, v);
    }
    mx = blockMax256(mx);
    float lsum = 0.f;
#pragma unroll
    for (int i = 0; i < 4; ++i) {
        s[i] = expf(s[i] - mx);
        lsum += s[i];
    }
    float tot = blockSum256(lsum);
    float inv = 1.0f / tot;
#pragma unroll
    for (int i = 0; i < 4; ++i) {
        int idx = t + 256 * i;
        prow[idx] = __float2half_rn(am[i] ? s[i] * inv : 0.0f);
    }
}

__global__ void gate_res_ln_kernel(const float* __restrict__ x,
                                   const float* __restrict__ lg,
                                   const float* __restrict__ lb) {
    int r = blockIdx.x;                       // (h*B + b)*N + n
    int t = threadIdx.x;
    int n = r & (Nn_SEQ - 1);
    int hb = r >> 10;
    int b = hb & (Bb - 1);
    int h = hb >> 3;
    long long idx = (long long)r * Dd + t;
    long long xrow = (long long)(b * Nn_SEQ + n) * Dd;

    float gv = __half2float(g_gt[idx]);
    float sig = 1.0f / (1.0f + expf(-gv));
    float val = g_o[idx] * sig + x[xrow + t];

    float mean = blockSum256(val) * (1.0f / Dd);
    float d = val - mean;
    float var = blockSum256(d * d) * (1.0f / Dd);
    float res = d * rsqrtf(var + EPSF) * lg[t] + lb[t];

    g_cat[(long long)(b * Nn_SEQ + n) * (Dd * Hh) + t * Hh + h] = __float2half_rn(res);
}

__global__ void final_kernel(const float* __restrict__ x,
                             const float* __restrict__ ob,
                             const float* __restrict__ lg,
                             const float* __restrict__ lb,
                             const int* __restrict__ mask,
                             float* __restrict__ out) {
    int r = blockIdx.x;                       // b*N + n
    int t = threadIdx.x;
    long long idx = (long long)r * Dd + t;
    float val = g_tmp[idx] + ob[t] + x[idx];
    float mean = blockSum256(val) * (1.0f / Dd);
    float d = val - mean;
    float var = blockSum256(d * d) * (1.0f / Dd);
    float res = d * rsqrtf(var + EPSF) * lg[t] + lb[t];
    out[idx] = res * (float)mask[r];
}

// ======================= launch ============================================
extern "C" void kernel_launch(void* const* d_in, const int* in_sizes, int n_in,
                              void* d_out, int out_size) {
    const float* x     = (const float*)d_in[0];
    const int*   mask  = (const int*)d_in[1];
    const float* wq    = (const float*)d_in[2];
    const float* wk    = (const float*)d_in[3];
    const float* wv    = (const float*)d_in[4];
    const float* wg    = (const float*)d_in[5];
    const float* out_w = (const float*)d_in[6];
    const float* out_b = (const float*)d_in[7];
    const float* ln_g  = (const float*)d_in[8];
    const float* ln_b  = (const float*)d_in[9];
    const float* lnr_g = (const float*)d_in[10];
    const float* lnr_b = (const float*)d_in[11];
    const float* lno_g = (const float*)d_in[12];
    const float* lno_b = (const float*)d_in[13];
    float* out = (float*)d_out;

    __half *pxn, *pq, *pk, *pg, *pvt, *pattp, *pcat;
    __half *pwqt, *pwkt, *pwvt, *pwgt, *powt;
    float *po, *patt, *ptmp;
    cudaGetSymbolAddress((void**)&pxn, g_xnorm);
    cudaGetSymbolAddress((void**)&pq, g_q);
    cudaGetSymbolAddress((void**)&pk, g_k);
    cudaGetSymbolAddress((void**)&pg, g_gt);
    cudaGetSymbolAddress((void**)&pvt, g_vt);
    cudaGetSymbolAddress((void**)&po, g_o);
    cudaGetSymbolAddress((void**)&patt, g_att);
    cudaGetSymbolAddress((void**)&pattp, g_attp);
    cudaGetSymbolAddress((void**)&pcat, g_cat);
    cudaGetSymbolAddress((void**)&ptmp, g_tmp);
    cudaGetSymbolAddress((void**)&pwqt, g_wqt);
    cudaGetSymbolAddress((void**)&pwkt, g_wkt);
    cudaGetSymbolAddress((void**)&pwvt, g_wvt);
    cudaGetSymbolAddress((void**)&pwgt, g_wgt);
    cudaGetSymbolAddress((void**)&powt, g_owt);

    const int Mtot = Bb * Nn_SEQ;                        // 8192
    const long long nd = (long long)Nn_SEQ * Dd;         // 262144
    const long long nn = (long long)Nn_SEQ * Nn_SEQ;     // 1048576
    const long long wsz = (long long)Dd * Dd;            // 65536

    // 0) weight transposes (W[K,N] fp32 -> W^T[N,K] fp16)
    {
        dim3 tb(32, 8);
        transpose_h_kernel<<<dim3(Dd / 32, Dd / 32, Hh), tb>>>(wq, pwqt, Dd, Dd);
        transpose_h_kernel<<<dim3(Dd / 32, Dd / 32, Hh), tb>>>(wk, pwkt, Dd, Dd);
        transpose_h_kernel<<<dim3(Dd / 32, Dd / 32, Hh), tb>>>(wv, pwvt, Dd, Dd);
        transpose_h_kernel<<<dim3(Dd / 32, Dd / 32, Hh), tb>>>(wg, pwgt, Dd, Dd);
        transpose_h_kernel<<<dim3(Dd / 32, (Dd * Hh) / 32, 1), tb>>>(out_w, powt, Dd * Hh, Dd);
    }

    // 1) LN(x) -> fp16
    ln_x_kernel<<<Mtot, 256>>>(x, ln_g, ln_b);

    // 2) q/k/gate projections: C[h] = x_norm @ W[h]  (M=8192, N=256, K=256)
    fp16_gemm_kernel<true><<<dim3(Dd / BN, Mtot / BM, 4), 256>>>(
        pxn, pwqt, pq, Dd, Dd, Dd, Dd, 0LL, wsz, 0LL, 1, (long long)Mtot * Dd, 1.0f);
    fp16_gemm_kernel<true><<<dim3(Dd / BN, Mtot / BM, 4), 256>>>(
        pxn, pwkt, pk, Dd, Dd, Dd, Dd, 0LL, wsz, 0LL, 1, (long long)Mtot * Dd, 1.0f);
    fp16_gemm_kernel<true><<<dim3(Dd / BN, Mtot / BM, 4), 256>>>(
        pxn, pwgt, pg, Dd, Dd, Dd, Dd, 0LL, wsz, 0LL, 1, (long long)Mtot * Dd, 1.0f);

    // 2b) v transposed: vt[h][e][bn]; A = wv^T [256,256], B = x_norm [8192,256]
    fp16_gemm_kernel<true><<<dim3(Mtot / BN, Dd / BM, 4), 256>>>(
        pwvt, pxn, pvt, Dd, Dd, Dd, Mtot, wsz, 0LL, 0LL, 1, (long long)Dd * Mtot, 1.0f);

    // 3) scores: att[z] = (1/16) q[z] @ k[z]^T  (fp32 out)
    fp16_gemm_kernel<false><<<dim3(Nn_SEQ / BN, Nn_SEQ / BM, Hh * Bb), 256>>>(
        pq, pk, patt, Dd, Dd, Dd, Nn_SEQ, nd, nd, 0LL, 1, nn, 0.0625f);

    // 4) masked softmax (fp32 scores -> fp16 probs)
    softmax_kernel<<<Hh * Bb * Nn_SEQ, 256>>>(mask);

    // 5) out = attp @ v  (fp32 out; B = vt slice [256,1024], row stride 8192)
    fp16_gemm_kernel<false><<<dim3(Dd / BN, Nn_SEQ / BM, Hh * Bb), 256>>>(
        pattp, pvt, po, Nn_SEQ, Nn_SEQ, Mtot, Dd,
        nn, (long long)Dd * Mtot, (long long)Nn_SEQ, Bb, nd, 1.0f);

    // 6) gate + residual + LN(lnr) + scatter to concat (fp16)
    gate_res_ln_kernel<<<Hh * Bb * Nn_SEQ, 256>>>(x, lnr_g, lnr_b);

    // 7) out projection: tmp = cat @ out_w  (fp32 out; M=8192, N=256, K=1024)
    fp16_gemm_kernel<false><<<dim3(Dd / BN, Mtot / BM, 1), 256>>>(
        pcat, powt, ptmp, Dd * Hh, Dd * Hh, Dd * Hh, Dd,
        0LL, 0LL, 0LL, 1, 0LL, 1.0f);

    // 8) + bias + x, LN(lno), * mask
    final_kernel<<<Mtot, 256>>>(x, out_b, lno_g, lno_b, mask, out);
}

// round 9
// speedup vs baseline: 6.1866x; 1.1172x over previous
#include <cuda_runtime.h>
#include <mma.h>
#include <cuda_fp16.h>
#include <cstdint>
#include <math.h>

using namespace nvcuda;

// Problem dims
#define Bb 8
#define Nn_SEQ 1024
#define Dd 256
#define Hh 4
#define EPSF 1e-6f

// ---------------- scratch (device globals; no allocation allowed) ----------
__device__ __align__(16) __half g_xnorm[Bb * Nn_SEQ * Dd];                 // 4 MB
__device__ __align__(16) __half g_q[Hh * Bb * Nn_SEQ * Dd];                // 16 MB
__device__ __align__(16) __half g_k[Hh * Bb * Nn_SEQ * Dd];                // 16 MB
__device__ __align__(16) __half g_gt[Hh * Bb * Nn_SEQ * Dd];               // 16 MB
__device__ __align__(16) __half g_vt[Hh * Dd * Bb * Nn_SEQ];               // 16 MB [h][e][b*N+n]
__device__ float g_o[Hh * Bb * Nn_SEQ * Dd];                               // 32 MB
__device__ float g_att[(long long)Hh * Bb * Nn_SEQ * Nn_SEQ];              // 128 MB (scores, fp32)
__device__ __align__(16) __half g_attp[(long long)Hh * Bb * Nn_SEQ * Nn_SEQ]; // 64 MB (probs, fp16)
__device__ __align__(16) __half g_cat[Bb * Nn_SEQ * Dd * Hh];              // 16 MB
__device__ float g_tmp[Bb * Nn_SEQ * Dd];                                  // 8 MB
__device__ __align__(16) __half g_wqt[Hh * Dd * Dd];
__device__ __align__(16) __half g_wkt[Hh * Dd * Dd];
__device__ __align__(16) __half g_wvt[Hh * Dd * Dd];
__device__ __align__(16) __half g_wgt[Hh * Dd * Dd];
__device__ __align__(16) __half g_owt[Dd * Dd * Hh];                       // [256][1024]

// ======================= cp.async helpers ==================================
__device__ __forceinline__ void cp16(void* dst, const void* src) {
    uint32_t d = (uint32_t)__cvta_generic_to_shared(dst);
    asm volatile("cp.async.ca.shared.global [%0], [%1], 16;"
                 :: "r"(d), "l"(src) : "memory");
}
__device__ __forceinline__ void cp_commit() {
    asm volatile("cp.async.commit_group;" ::: "memory");
}
__device__ __forceinline__ void cp_wait1() {
    asm volatile("cp.async.wait_group 1;" ::: "memory");
}

// ======================= FP16 WMMA GEMM ====================================
// C[M, N] = alpha * A[M, K] @ B[N, K]^T  (A, B fp16 K-major; fp32 accumulate;
// output fp32 or fp16 by template).
// BM=BN=128, BK=32. 128 threads = 4 warps (2 x 2), warp tile 64 x 64
// (4 x 4 wmma 16x16x16 tiles). cp.async double-buffered smem.
#define BM 128
#define BN 128
#define BK 32
#define PADH 40   // halves per row (32 data + 8 pad) = 80 B

template <bool OUTH>
__global__ void __launch_bounds__(128, 2)
fp16_gemm_kernel(const __half* __restrict__ A, const __half* __restrict__ B,
                 void* __restrict__ Cv, int K, int lda, int ldb, int ldc,
                 long long bsA, long long bsB1, long long bsB2, int zdivB,
                 long long bsC, float alpha) {
    __shared__ __half sA[2][BM][PADH];
    __shared__ __half sB[2][BN][PADH];

    int tid = threadIdx.x, wid = tid >> 5, lane = tid & 31;
    int z = blockIdx.z;
    A += (long long)z * bsA;
    B += (long long)(z / zdivB) * bsB1 + (long long)(z % zdivB) * bsB2;
    int m0 = blockIdx.y * BM;
    int n0 = blockIdx.x * BN;

    int warp_m = (wid & 1) * 64;      // 2 warps along M, 4 tiles of 16
    int warp_n = (wid >> 1) * 64;     // 2 warps along N, 4 tiles of 16

    wmma::fragment<wmma::accumulator, 16, 16, 16, float> acc[4][4];
#pragma unroll
    for (int mt = 0; mt < 4; ++mt)
#pragma unroll
        for (int nt = 0; nt < 4; ++nt)
            wmma::fill_fragment(acc[mt][nt], 0.0f);

    int nchunks = K / BK;

    // staging: per matrix per chunk = 128 rows x 64 B = 512 x 16B
    // 128 threads -> 4 cp.async each per matrix
    auto stage = [&](int s, int k0) {
#pragma unroll
        for (int i = 0; i < 4; ++i) {
            int idx = tid + 128 * i;
            int r = idx >> 2, c8 = (idx & 3) * 8;
            cp16(&sA[s][r][c8], A + (long long)(m0 + r) * lda + k0 + c8);
            cp16(&sB[s][r][c8], B + (long long)(n0 + r) * ldb + k0 + c8);
        }
    };

    stage(0, 0);
    cp_commit();
    if (nchunks > 1) stage(1, BK);
    cp_commit();

    for (int c = 0; c < nchunks; ++c) {
        int s = c & 1;
        cp_wait1();              // chunk c resident (all but latest group done)
        __syncthreads();

#pragma unroll
        for (int ks = 0; ks < 2; ++ks) {
            wmma::fragment<wmma::matrix_a, 16, 16, 16, __half, wmma::row_major> fa[4];
            wmma::fragment<wmma::matrix_b, 16, 16, 16, __half, wmma::col_major> fb[4];
#pragma unroll
            for (int mt = 0; mt < 4; ++mt)
                wmma::load_matrix_sync(fa[mt], &sA[s][warp_m + mt * 16][ks * 16], PADH);
#pragma unroll
            for (int nt = 0; nt < 4; ++nt)
                wmma::load_matrix_sync(fb[nt], &sB[s][warp_n + nt * 16][ks * 16], PADH);
#pragma unroll
            for (int mt = 0; mt < 4; ++mt)
#pragma unroll
                for (int nt = 0; nt < 4; ++nt)
                    wmma::mma_sync(acc[mt][nt], fa[mt], fb[nt], acc[mt][nt]);
        }

        __syncthreads();         // all warps done reading buf s
        if (c + 2 < nchunks) stage(s, (c + 2) * BK);
        cp_commit();             // always commit (possibly empty group)
    }

    // ---- epilogue --------------------------------------------------------
#pragma unroll
    for (int mt = 0; mt < 4; ++mt)
#pragma unroll
        for (int nt = 0; nt < 4; ++nt)
#pragma unroll
            for (int e = 0; e < acc[mt][nt].num_elements; ++e)
                acc[mt][nt].x[e] *= alpha;

    if (!OUTH) {
        float* C = (float*)Cv + (long long)z * bsC;
#pragma unroll
        for (int mt = 0; mt < 4; ++mt)
#pragma unroll
            for (int nt = 0; nt < 4; ++nt) {
                float* cp = C + (long long)(m0 + warp_m + mt * 16) * ldc
                              + (n0 + warp_n + nt * 16);
                wmma::store_matrix_sync(cp, acc[mt][nt], ldc, wmma::mem_row_major);
            }
    } else {
        __half* C = (__half*)Cv + (long long)z * bsC;
        __syncthreads();   // done with sA/sB; reuse as fp32 bounce buffers
        float* wstage = reinterpret_cast<float*>(&sA[0][0][0]) + wid * 256;
        int lrow = lane >> 1, lcol = (lane & 1) * 8;
#pragma unroll
        for (int mt = 0; mt < 4; ++mt)
#pragma unroll
            for (int nt = 0; nt < 4; ++nt) {
                wmma::store_matrix_sync(wstage, acc[mt][nt], 16, wmma::mem_row_major);
                __syncwarp();
                const float* src = wstage + lrow * 16 + lcol;
                __half2 h0 = __floats2half2_rn(src[0], src[1]);
                __half2 h1 = __floats2half2_rn(src[2], src[3]);
                __half2 h2 = __floats2half2_rn(src[4], src[5]);
                __half2 h3 = __floats2half2_rn(src[6], src[7]);
                uint4 pk;
                pk.x = *reinterpret_cast<uint32_t*>(&h0);
                pk.y = *reinterpret_cast<uint32_t*>(&h1);
                pk.z = *reinterpret_cast<uint32_t*>(&h2);
                pk.w = *reinterpret_cast<uint32_t*>(&h3);
                __half* cp = C + (long long)(m0 + warp_m + mt * 16 + lrow) * ldc
                               + (n0 + warp_n + nt * 16 + lcol);
                *reinterpret_cast<uint4*>(cp) = pk;
                __syncwarp();
            }
    }
}

// ======================= transposes (weights -> fp16) ======================
struct Ptr4 { const float* p[4]; };
struct HPtr4 { __half* p[4]; };

// z = which*Hh + h : transposes all 4 head-weight tensors in one launch
__global__ void transpose4_h_kernel(Ptr4 in4, HPtr4 out4) {
    __shared__ float t[32][33];
    int which = blockIdx.z >> 2, h = blockIdx.z & 3;
    const float* in = in4.p[which] + (long long)h * Dd * Dd;
    __half* out = out4.p[which] + (long long)h * Dd * Dd;
    int c0 = blockIdx.x * 32, r0 = blockIdx.y * 32;
    int x = threadIdx.x, y = threadIdx.y;
#pragma unroll
    for (int i = 0; i < 32; i += 8)
        t[y + i][x] = in[(long long)(r0 + y + i) * Dd + c0 + x];
    __syncthreads();
#pragma unroll
    for (int i = 0; i < 32; i += 8)
        out[(long long)(c0 + y + i) * Dd + r0 + x] = __float2half_rn(t[x][y + i]);
}

__global__ void transpose_h_kernel(const float* __restrict__ in, __half* __restrict__ out,
                                   int R, int C) {
    __shared__ float t[32][33];
    int c0 = blockIdx.x * 32, r0 = blockIdx.y * 32;
    int x = threadIdx.x, y = threadIdx.y;
#pragma unroll
    for (int i = 0; i < 32; i += 8)
        t[y + i][x] = in[(long long)(r0 + y + i) * C + c0 + x];
    __syncthreads();
#pragma unroll
    for (int i = 0; i < 32; i += 8)
        out[(long long)(c0 + y + i) * R + r0 + x] = __float2half_rn(t[x][y + i]);
}

// ======================= reductions (blocks of 256) ========================
__device__ __forceinline__ float warpSum(float v) {
    v += __shfl_down_sync(0xffffffffu, v, 16);
    v += __shfl_down_sync(0xffffffffu, v, 8);
    v += __shfl_down_sync(0xffffffffu, v, 4);
    v += __shfl_down_sync(0xffffffffu, v, 2);
    v += __shfl_down_sync(0xffffffffu, v, 1);
    return v;
}
__device__ __forceinline__ float warpMax(float v) {
    v = fmaxf(v, __shfl_down_sync(0xffffffffu, v, 16));
    v = fmaxf(v, __shfl_down_sync(0xffffffffu, v, 8));
    v = fmaxf(v, __shfl_down_sync(0xffffffffu, v, 4));
    v = fmaxf(v, __shfl_down_sync(0xffffffffu, v, 2));
    v = fmaxf(v, __shfl_down_sync(0xffffffffu, v, 1));
    return v;
}
__device__ float blockSum256(float v) {
    __shared__ float s[8];
    int w = threadIdx.x >> 5, l = threadIdx.x & 31;
    v = warpSum(v);
    if (l == 0) s[w] = v;
    __syncthreads();
    if (w == 0) {
        float t = (l < 8) ? s[l] : 0.f;
        t = warpSum(t);
        if (l == 0) s[0] = t;
    }
    __syncthreads();
    float r = s[0];
    __syncthreads();
    return r;
}
__device__ float blockMax256(float v) {
    __shared__ float s[8];
    int w = threadIdx.x >> 5, l = threadIdx.x & 31;
    v = warpMax(v);
    if (l == 0) s[w] = v;
    __syncthreads();
    if (w == 0) {
        float t = (l < 8) ? s[l] : -3.4e38f;
        t = warpMax(t);
        if (l == 0) s[0] = t;
    }
    __syncthreads();
    float r = s[0];
    __syncthreads();
    return r;
}

// ======================= elementwise kernels ===============================
__global__ void ln_x_kernel(const float* __restrict__ x,
                            const float* __restrict__ g, const float* __restrict__ b) {
    long long row = blockIdx.x;
    int t = threadIdx.x;
    float v = x[row * Dd + t];
    float mean = blockSum256(v) * (1.0f / Dd);
    float d = v - mean;
    float var = blockSum256(d * d) * (1.0f / Dd);
    g_xnorm[row * Dd + t] = __float2half_rn(d * rsqrtf(var + EPSF) * g[t] + b[t]);
}

__global__ void softmax_kernel(const int* __restrict__ mask) {
    int r = blockIdx.x;                       // (h*B + b)*N + n
    int n = r & (Nn_SEQ - 1);
    int hb = r >> 10;
    int b = hb & (Bb - 1);
    const float* row = g_att + (long long)r * Nn_SEQ;
    __half* prow = g_attp + (long long)r * Nn_SEQ;
    int t = threadIdx.x;

    int mn = mask[b * Nn_SEQ + n];
    float s[4];
    int am[4];
    float mx = -3.4e38f;
#pragma unroll
    for (int i = 0; i < 4; ++i) {
        int idx = t + 256 * i;
        int mm = mask[b * Nn_SEQ + idx];
        am[i] = mn * mm;
        float v = row[idx];
        v = v + (1.0f - (float)am[i]) * (-1e9f);
        s[i] = v;
        mx = fmaxf(mx, v);
    }
    mx = blockMax256(mx);
    float lsum = 0.f;
#pragma unroll
    for (int i = 0; i < 4; ++i) {
        s[i] = expf(s[i] - mx);
        lsum += s[i];
    }
    float tot = blockSum256(lsum);
    float inv = 1.0f / tot;
#pragma unroll
    for (int i = 0; i < 4; ++i) {
        int idx = t + 256 * i;
        prow[idx] = __float2half_rn(am[i] ? s[i] * inv : 0.0f);
    }
}

__global__ void gate_res_ln_kernel(const float* __restrict__ x,
                                   const float* __restrict__ lg,
                                   const float* __restrict__ lb) {
    int r = blockIdx.x;                       // (h*B + b)*N + n
    int t = threadIdx.x;
    int n = r & (Nn_SEQ - 1);
    int hb = r >> 10;
    int b = hb & (Bb - 1);
    int h = hb >> 3;
    long long idx = (long long)r * Dd + t;
    long long xrow = (long long)(b * Nn_SEQ + n) * Dd;

    float gv = __half2float(g_gt[idx]);
    float sig = 1.0f / (1.0f + expf(-gv));
    float val = g_o[idx] * sig + x[xrow + t];

    float mean = blockSum256(val) * (1.0f / Dd);
    float d = val - mean;
    float var = blockSum256(d * d) * (1.0f / Dd);
    float res = d * rsqrtf(var + EPSF) * lg[t] + lb[t];

    g_cat[(long long)(b * Nn_SEQ + n) * (Dd * Hh) + t * Hh + h] = __float2half_rn(res);
}

__global__ void final_kernel(const float* __restrict__ x,
                             const float* __restrict__ ob,
                             const float* __restrict__ lg,
                             const float* __restrict__ lb,
                             const int* __restrict__ mask,
                             float* __restrict__ out) {
    int r = blockIdx.x;                       // b*N + n
    int t = threadIdx.x;
    long long idx = (long long)r * Dd + t;
    float val = g_tmp[idx] + ob[t] + x[idx];
    float mean = blockSum256(val) * (1.0f / Dd);
    float d = val - mean;
    float var = blockSum256(d * d) * (1.0f / Dd);
    float res = d * rsqrtf(var + EPSF) * lg[t] + lb[t];
    out[idx] = res * (float)mask[r];
}

// ======================= launch ============================================
extern "C" void kernel_launch(void* const* d_in, const int* in_sizes, int n_in,
                              void* d_out, int out_size) {
    const float* x     = (const float*)d_in[0];
    const int*   mask  = (const int*)d_in[1];
    const float* wq    = (const float*)d_in[2];
    const float* wk    = (const float*)d_in[3];
    const float* wv    = (const float*)d_in[4];
    const float* wg    = (const float*)d_in[5];
    const float* out_w = (const float*)d_in[6];
    const float* out_b = (const float*)d_in[7];
    const float* ln_g  = (const float*)d_in[8];
    const float* ln_b  = (const float*)d_in[9];
    const float* lnr_g = (const float*)d_in[10];
    const float* lnr_b = (const float*)d_in[11];
    const float* lno_g = (const float*)d_in[12];
    const float* lno_b = (const float*)d_in[13];
    float* out = (float*)d_out;

    __half *pxn, *pq, *pk, *pg, *pvt, *pattp, *pcat;
    __half *pwqt, *pwkt, *pwvt, *pwgt, *powt;
    float *po, *patt, *ptmp;
    cudaGetSymbolAddress((void**)&pxn, g_xnorm);
    cudaGetSymbolAddress((void**)&pq, g_q);
    cudaGetSymbolAddress((void**)&pk, g_k);
    cudaGetSymbolAddress((void**)&pg, g_gt);
    cudaGetSymbolAddress((void**)&pvt, g_vt);
    cudaGetSymbolAddress((void**)&po, g_o);
    cudaGetSymbolAddress((void**)&patt, g_att);
    cudaGetSymbolAddress((void**)&pattp, g_attp);
    cudaGetSymbolAddress((void**)&pcat, g_cat);
    cudaGetSymbolAddress((void**)&ptmp, g_tmp);
    cudaGetSymbolAddress((void**)&pwqt, g_wqt);
    cudaGetSymbolAddress((void**)&pwkt, g_wkt);
    cudaGetSymbolAddress((void**)&pwvt, g_wvt);
    cudaGetSymbolAddress((void**)&pwgt, g_wgt);
    cudaGetSymbolAddress((void**)&powt, g_owt);

    const int Mtot = Bb * Nn_SEQ;                        // 8192
    const long long nd = (long long)Nn_SEQ * Dd;         // 262144
    const long long nn = (long long)Nn_SEQ * Nn_SEQ;     // 1048576
    const long long wsz = (long long)Dd * Dd;            // 65536

    // 0) weight transposes (W[K,N] fp32 -> W^T[N,K] fp16) — batched
    {
        dim3 tb(32, 8);
        Ptr4 in4; in4.p[0] = wq; in4.p[1] = wk; in4.p[2] = wv; in4.p[3] = wg;
        HPtr4 out4; out4.p[0] = pwqt; out4.p[1] = pwkt; out4.p[2] = pwvt; out4.p[3] = pwgt;
        transpose4_h_kernel<<<dim3(Dd / 32, Dd / 32, 16), tb>>>(in4, out4);
        transpose_h_kernel<<<dim3(Dd / 32, (Dd * Hh) / 32, 1), tb>>>(out_w, powt, Dd * Hh, Dd);
    }

    // 1) LN(x) -> fp16
    ln_x_kernel<<<Mtot, 256>>>(x, ln_g, ln_b);

    // 2) q/k/gate projections: C[h] = x_norm @ W[h]  (M=8192, N=256, K=256)
    fp16_gemm_kernel<true><<<dim3(Dd / BN, Mtot / BM, 4), 128>>>(
        pxn, pwqt, pq, Dd, Dd, Dd, Dd, 0LL, wsz, 0LL, 1, (long long)Mtot * Dd, 1.0f);
    fp16_gemm_kernel<true><<<dim3(Dd / BN, Mtot / BM, 4), 128>>>(
        pxn, pwkt, pk, Dd, Dd, Dd, Dd, 0LL, wsz, 0LL, 1, (long long)Mtot * Dd, 1.0f);
    fp16_gemm_kernel<true><<<dim3(Dd / BN, Mtot / BM, 4), 128>>>(
        pxn, pwgt, pg, Dd, Dd, Dd, Dd, 0LL, wsz, 0LL, 1, (long long)Mtot * Dd, 1.0f);

    // 2b) v transposed: vt[h][e][bn]; A = wv^T [256,256], B = x_norm [8192,256]
    fp16_gemm_kernel<true><<<dim3(Mtot / BN, Dd / BM, 4), 128>>>(
        pwvt, pxn, pvt, Dd, Dd, Dd, Mtot, wsz, 0LL, 0LL, 1, (long long)Dd * Mtot, 1.0f);

    // 3) scores: att[z] = (1/16) q[z] @ k[z]^T  (fp32 out)
    fp16_gemm_kernel<false><<<dim3(Nn_SEQ / BN, Nn_SEQ / BM, Hh * Bb), 128>>>(
        pq, pk, patt, Dd, Dd, Dd, Nn_SEQ, nd, nd, 0LL, 1, nn, 0.0625f);

    // 4) masked softmax (fp32 scores -> fp16 probs)
    softmax_kernel<<<Hh * Bb * Nn_SEQ, 256>>>(mask);

    // 5) out = attp @ v  (fp32 out; B = vt slice [256,1024], row stride 8192)
    fp16_gemm_kernel<false><<<dim3(Dd / BN, Nn_SEQ / BM, Hh * Bb), 128>>>(
        pattp, pvt, po, Nn_SEQ, Nn_SEQ, Mtot, Dd,
        nn, (long long)Dd * Mtot, (long long)Nn_SEQ, Bb, nd, 1.0f);

    // 6) gate + residual + LN(lnr) + scatter to concat (fp16)
    gate_res_ln_kernel<<<Hh * Bb * Nn_SEQ, 256>>>(x, lnr_g, lnr_b);

    // 7) out projection: tmp = cat @ out_w  (fp32 out; M=8192, N=256, K=1024)
    fp16_gemm_kernel<false><<<dim3(Dd / BN, Mtot / BM, 1), 128>>>(
        pcat, powt, ptmp, Dd * Hh, Dd * Hh, Dd * Hh, Dd,
        0LL, 0LL, 0LL, 1, 0LL, 1.0f);

    // 8) + bias + x, LN(lno), * mask
    final_kernel<<<Mtot, 256>>>(x, out_b, lno_g, lno_b, mask, out);
}